// round 3
// baseline (speedup 1.0000x reference)
#include <cuda_runtime.h>
#include <math.h>

#define BB 4
#define FF 1024
#define SS 2048
#define II 2048
#define EE 8
#define KW 5
#define OUTF 3072          // G*F
#define NT 8192            // B*S

// ---------------- scratch (static __device__, no allocation) ----------------
__device__ float g_xT[NT * FF];            // [token, F]           32 MB
__device__ float g_h0tok[NT * II];         // [token, I]           64 MB
__device__ float g_h0cs[BB * II * SS];     // [b, c, s] relu'd     64 MB
__device__ float g_h1tok[NT * II];         // [token, I] relu'd    64 MB
__device__ float g_h2tok[NT * OUTF];       // [token, 3F]          96 MB
__device__ int   g_cnt0[EE];
__device__ int   g_cnt2[EE];
__device__ int   g_list0[EE * NT];
__device__ int   g_list2[EE * NT];

// ---------------- utilities ----------------
__global__ void zero_counts_kernel() {
    if (threadIdx.x < EE) { g_cnt0[threadIdx.x] = 0; g_cnt2[threadIdx.x] = 0; }
}

// inp [B,F,S] -> xT [B*S, F]
__global__ void transpose_in_kernel(const float* __restrict__ in, float* __restrict__ xT) {
    __shared__ float tile[32][33];
    const int b = blockIdx.z;
    const int f0 = blockIdx.y * 32, s0 = blockIdx.x * 32;
    const int tx = threadIdx.x, ty = threadIdx.y;
    #pragma unroll
    for (int r = 0; r < 32; r += 8)
        tile[ty + r][tx] = in[((size_t)b * FF + f0 + ty + r) * SS + s0 + tx];
    __syncthreads();
    #pragma unroll
    for (int r = 0; r < 32; r += 8)
        xT[((size_t)b * SS + s0 + ty + r) * FF + f0 + tx] = tile[tx][ty + r];
}

// h0tok [B*S, I] -> h0cs [B, I, S] with relu
__global__ void transpose_relu_kernel(const float* __restrict__ h0tok, float* __restrict__ h0cs) {
    __shared__ float tile[32][33];
    const int b = blockIdx.z;
    const int i0 = blockIdx.y * 32, s0 = blockIdx.x * 32;
    const int tx = threadIdx.x, ty = threadIdx.y;
    #pragma unroll
    for (int r = 0; r < 32; r += 8)
        tile[ty + r][tx] = h0tok[((size_t)b * SS + s0 + ty + r) * II + i0 + tx];
    __syncthreads();
    #pragma unroll
    for (int r = 0; r < 32; r += 8)
        h0cs[((size_t)b * II + i0 + ty + r) * SS + s0 + tx] = fmaxf(tile[tx][ty + r], 0.0f);
}

// ---------------- gating: logits + argmax + per-expert token lists ----------------
template<int KD>
__global__ __launch_bounds__(256) void gate_kernel(const float* __restrict__ X,
                                                   const float* __restrict__ Gw,
                                                   int* __restrict__ cnt,
                                                   int* __restrict__ list) {
    const int t = blockIdx.x;
    const float* x = X + (size_t)t * KD;
    float acc[EE];
    #pragma unroll
    for (int e = 0; e < EE; e++) acc[e] = 0.0f;
    for (int f = threadIdx.x; f < KD; f += 256) {
        const float xv = x[f];
        #pragma unroll
        for (int e = 0; e < EE; e++) acc[e] += xv * Gw[e * KD + f];
    }
    __shared__ float red[EE][256];
    #pragma unroll
    for (int e = 0; e < EE; e++) red[e][threadIdx.x] = acc[e];
    __syncthreads();
    for (int srt = 128; srt > 0; srt >>= 1) {
        if (threadIdx.x < srt) {
            #pragma unroll
            for (int e = 0; e < EE; e++) red[e][threadIdx.x] += red[e][threadIdx.x + srt];
        }
        __syncthreads();
    }
    if (threadIdx.x == 0) {
        int best = 0; float bv = red[0][0];
        #pragma unroll
        for (int e = 1; e < EE; e++) { const float v = red[e][0]; if (v > bv) { bv = v; best = e; } }
        const int pos = atomicAdd(&cnt[best], 1);
        list[best * NT + pos] = t;
    }
}

// ---------------- grouped expert GEMM: out[tok, n] = X[tok, :] @ W[e] ----------------
// 64 tokens x 128 n per block, BK=16, 256 threads, 4x8 micro-tile.
template<int KD, int ND>
__global__ __launch_bounds__(256) void moe_gemm_kernel(const float* __restrict__ X,
                                                       const float* __restrict__ W,
                                                       const int* __restrict__ cnt,
                                                       const int* __restrict__ list,
                                                       float* __restrict__ out) {
    const int e = blockIdx.z;
    const int ce = cnt[e];
    const int m0 = blockIdx.y * 64;
    if (m0 >= ce) return;
    const int n0 = blockIdx.x * 128;
    const float* We = W + (size_t)e * KD * ND;

    __shared__ int   toks[64];
    __shared__ float As[16][68];
    __shared__ float Bs[16][132];

    const int tid = threadIdx.x;
    if (tid < 64) {
        const int m = m0 + tid;
        toks[tid] = list[e * NT + (m < ce ? m : m0)];
    }
    __syncthreads();

    const int tx = tid & 15, ty = tid >> 4;
    const int la_m = tid >> 2;
    const int la_k = (tid & 3) << 2;
    const int lb_k = tid >> 4;
    const int lb_n = (tid & 15) << 3;
    const float* xrow = X + (size_t)toks[la_m] * KD + la_k;

    float acc[4][8];
    #pragma unroll
    for (int i = 0; i < 4; i++)
        #pragma unroll
        for (int j = 0; j < 8; j++) acc[i][j] = 0.0f;

    for (int k0 = 0; k0 < KD; k0 += 16) {
        const float4 av = *(const float4*)(xrow + k0);
        As[la_k + 0][la_m] = av.x;
        As[la_k + 1][la_m] = av.y;
        As[la_k + 2][la_m] = av.z;
        As[la_k + 3][la_m] = av.w;
        const float* wp = We + (size_t)(k0 + lb_k) * ND + n0 + lb_n;
        *(float4*)&Bs[lb_k][lb_n]     = *(const float4*)wp;
        *(float4*)&Bs[lb_k][lb_n + 4] = *(const float4*)(wp + 4);
        __syncthreads();
        #pragma unroll
        for (int kk = 0; kk < 16; kk++) {
            const float4 a  = *(const float4*)&As[kk][ty << 2];
            const float4 b0 = *(const float4*)&Bs[kk][tx << 3];
            const float4 b1 = *(const float4*)&Bs[kk][(tx << 3) + 4];
            const float avv[4] = {a.x, a.y, a.z, a.w};
            const float bvv[8] = {b0.x, b0.y, b0.z, b0.w, b1.x, b1.y, b1.z, b1.w};
            #pragma unroll
            for (int i = 0; i < 4; i++)
                #pragma unroll
                for (int j = 0; j < 8; j++) acc[i][j] += avv[i] * bvv[j];
        }
        __syncthreads();
    }
    #pragma unroll
    for (int i = 0; i < 4; i++) {
        const int m = m0 + (ty << 2) + i;
        if (m < ce) {
            float* dst = out + (size_t)toks[(ty << 2) + i] * ND + n0 + (tx << 3);
            *(float4*)dst       = make_float4(acc[i][0], acc[i][1], acc[i][2], acc[i][3]);
            *((float4*)dst + 1) = make_float4(acc[i][4], acc[i][5], acc[i][6], acc[i][7]);
        }
    }
}

// ---------------- causal conv as implicit-im2col GEMM + relu, token-major out ----------------
// out[b,o,s] = sum_{c,k} W1[o,c,k] * h0cs[b,c,s+k-4];  writes relu to h1tok[(b*S+s)*I + o]
__global__ __launch_bounds__(256) void conv_kernel(const float* __restrict__ Xc,
                                                   const float* __restrict__ W1,
                                                   float* __restrict__ Ytok) {
    const int s0 = blockIdx.x * 64;
    const int b  = blockIdx.y;
    const int o0 = blockIdx.z * 128;

    __shared__ float Ws[80][132];   // [cc*5+k][o]
    __shared__ float Xs[16][72];    // [cc][j], j in [0,68): s = s0-4+j

    const int tid = threadIdx.x;
    const int tx = tid & 15, ty = tid >> 4;

    float acc[8][4];
    #pragma unroll
    for (int i = 0; i < 8; i++)
        #pragma unroll
        for (int j = 0; j < 4; j++) acc[i][j] = 0.0f;

    const float* w1base = W1 + (size_t)o0 * (II * KW);
    const float* xbase  = Xc + (size_t)b * II * SS;

    for (int c0 = 0; c0 < II; c0 += 16) {
        for (int idx = tid; idx < 128 * 80; idx += 256) {
            const int o = idx / 80;
            const int r = idx - o * 80;                 // r = cc*5 + k
            Ws[r][o] = w1base[(size_t)o * (II * KW) + c0 * KW + r];
        }
        for (int idx = tid; idx < 16 * 68; idx += 256) {
            const int cc = idx / 68;
            const int j  = idx - cc * 68;
            const int s  = s0 + j - 4;
            Xs[cc][j] = (s >= 0) ? xbase[(size_t)(c0 + cc) * SS + s] : 0.0f;
        }
        __syncthreads();
        #pragma unroll 4
        for (int cc = 0; cc < 16; cc++) {
            float xr[8];
            const float4 xa = *(const float4*)&Xs[cc][tx << 2];
            const float4 xb = *(const float4*)&Xs[cc][(tx << 2) + 4];
            xr[0] = xa.x; xr[1] = xa.y; xr[2] = xa.z; xr[3] = xa.w;
            xr[4] = xb.x; xr[5] = xb.y; xr[6] = xb.z; xr[7] = xb.w;
            #pragma unroll
            for (int k = 0; k < KW; k++) {
                const float4 wa = *(const float4*)&Ws[cc * KW + k][ty << 3];
                const float4 wb = *(const float4*)&Ws[cc * KW + k][(ty << 3) + 4];
                const float wr[8] = {wa.x, wa.y, wa.z, wa.w, wb.x, wb.y, wb.z, wb.w};
                #pragma unroll
                for (int i = 0; i < 8; i++)
                    #pragma unroll
                    for (int j = 0; j < 4; j++)
                        acc[i][j] += wr[i] * xr[j + k];
            }
        }
        __syncthreads();
    }
    #pragma unroll
    for (int j = 0; j < 4; j++) {
        const int s = s0 + (tx << 2) + j;
        float* dst = Ytok + ((size_t)b * SS + s) * II + o0 + (ty << 3);
        *(float4*)dst = make_float4(fmaxf(acc[0][j], 0.f), fmaxf(acc[1][j], 0.f),
                                    fmaxf(acc[2][j], 0.f), fmaxf(acc[3][j], 0.f));
        *((float4*)dst + 1) = make_float4(fmaxf(acc[4][j], 0.f), fmaxf(acc[5][j], 0.f),
                                          fmaxf(acc[6][j], 0.f), fmaxf(acc[7][j], 0.f));
    }
}

// ---------------- cumsum(feature) / divisor * scale + shift, center, norm, *0.25 ----------------
__global__ __launch_bounds__(256) void final_kernel(const float* __restrict__ H,
                                                    const float* __restrict__ divisor,
                                                    float* __restrict__ out) {
    const int t = blockIdx.x;
    const int b = t >> 11;          // t / SS
    const int s = t & (SS - 1);
    const float* h = H + (size_t)t * OUTF;
    const int tid = threadIdx.x;
    const int lane = tid & 31, wid = tid >> 5;

    // thread-local inclusive prefix over 4 consecutive depth values
    const float4 d4 = *(const float4*)(h + (tid << 2));
    const float v0 = d4.x;
    const float v1 = v0 + d4.y;
    const float v2 = v1 + d4.z;
    const float v3 = v2 + d4.w;
    const float tsum = v3;

    // warp inclusive scan of thread sums
    float xsc = tsum;
    #pragma unroll
    for (int o = 1; o < 32; o <<= 1) {
        const float y = __shfl_up_sync(0xffffffffu, xsc, o);
        if (lane >= o) xsc += y;
    }
    __shared__ float wsum[8];
    __shared__ float woff[8];
    if (lane == 31) wsum[wid] = xsc;
    __syncthreads();
    if (tid == 0) { float r = 0.f; for (int w = 0; w < 8; w++) { woff[w] = r; r += wsum[w]; } }
    __syncthreads();
    const float off = woff[wid] + (xsc - tsum);

    const float invd = 1.0f / divisor[s];
    const float4 sc  = *(const float4*)(h + FF + (tid << 2));
    const float4 sh  = *(const float4*)(h + 2 * FF + (tid << 2));
    const float o0 = (v0 + off) * invd * sc.x + sh.x;
    const float o1 = (v1 + off) * invd * sc.y + sh.y;
    const float o2 = (v2 + off) * invd * sc.z + sh.z;
    const float o3 = (v3 + off) * invd * sc.w + sh.w;

    // mean over features
    float s1 = o0 + o1 + o2 + o3;
    #pragma unroll
    for (int o = 16; o > 0; o >>= 1) s1 += __shfl_xor_sync(0xffffffffu, s1, o);
    __shared__ float r1[8];
    __shared__ float s_mean;
    if (lane == 0) r1[wid] = s1;
    __syncthreads();
    if (tid == 0) { float a = 0.f; for (int w = 0; w < 8; w++) a += r1[w]; s_mean = a * (1.0f / FF); }
    __syncthreads();
    const float mean = s_mean;

    // centered norm
    const float c0 = o0 - mean, c1 = o1 - mean, c2 = o2 - mean, c3 = o3 - mean;
    float s2 = c0 * c0 + c1 * c1 + c2 * c2 + c3 * c3;
    #pragma unroll
    for (int o = 16; o > 0; o >>= 1) s2 += __shfl_xor_sync(0xffffffffu, s2, o);
    __shared__ float r2[8];
    __shared__ float s_scale;
    if (lane == 0) r2[wid] = s2;
    __syncthreads();
    if (tid == 0) {
        float a = 0.f;
        for (int w = 0; w < 8; w++) a += r2[w];
        const float denom = sqrtf(a) * (1.0f / 32.0f) + 1e-5f;  // ||c|| * F^-0.5 + eps
        s_scale = 0.25f / denom;                                // * INIT_SCALE
    }
    __syncthreads();
    const float k = s_scale;

    float* op = out + ((size_t)b * FF + (tid << 2)) * SS + s;
    op[0]          = c0 * k;
    op[SS]         = c1 * k;
    op[2 * (size_t)SS] = c2 * k;
    op[3 * (size_t)SS] = c3 * k;
}

// ---------------- launch ----------------
extern "C" void kernel_launch(void* const* d_in, const int* in_sizes, int n_in,
                              void* d_out, int out_size) {
    (void)in_sizes; (void)n_in; (void)out_size;
    const float* inp     = (const float*)d_in[0];
    const float* divisor = (const float*)d_in[1];
    const float* w0g     = (const float*)d_in[2];
    const float* w0      = (const float*)d_in[3];
    const float* w1      = (const float*)d_in[4];
    const float* w2g     = (const float*)d_in[5];
    const float* w2      = (const float*)d_in[6];
    float* out = (float*)d_out;

    float *xT, *h0tok, *h0cs, *h1tok, *h2tok;
    int *cnt0, *cnt2, *list0, *list2;
    cudaGetSymbolAddress((void**)&xT,    g_xT);
    cudaGetSymbolAddress((void**)&h0tok, g_h0tok);
    cudaGetSymbolAddress((void**)&h0cs,  g_h0cs);
    cudaGetSymbolAddress((void**)&h1tok, g_h1tok);
    cudaGetSymbolAddress((void**)&h2tok, g_h2tok);
    cudaGetSymbolAddress((void**)&cnt0,  g_cnt0);
    cudaGetSymbolAddress((void**)&cnt2,  g_cnt2);
    cudaGetSymbolAddress((void**)&list0, g_list0);
    cudaGetSymbolAddress((void**)&list2, g_list2);

    zero_counts_kernel<<<1, 32>>>();
    transpose_in_kernel<<<dim3(SS / 32, FF / 32, BB), dim3(32, 8)>>>(inp, xT);
    gate_kernel<FF><<<NT, 256>>>(xT, w0g, cnt0, list0);
    moe_gemm_kernel<FF, II><<<dim3(II / 128, NT / 64, EE), 256>>>(xT, w0, cnt0, list0, h0tok);
    transpose_relu_kernel<<<dim3(SS / 32, II / 32, BB), dim3(32, 8)>>>(h0tok, h0cs);
    conv_kernel<<<dim3(SS / 64, BB, II / 128), 256>>>(h0cs, w1, h1tok);
    gate_kernel<II><<<NT, 256>>>(h1tok, w2g, cnt2, list2);
    moe_gemm_kernel<II, OUTF><<<dim3(OUTF / 128, NT / 64, EE), 256>>>(h1tok, w2, cnt2, list2, h2tok);
    final_kernel<<<NT, 256>>>(h2tok, divisor, out);
}

// round 4
// speedup vs baseline: 1.0023x; 1.0023x over previous
#include <cuda_runtime.h>
#include <math.h>

#define BB 4
#define FF 1024
#define SS 2048
#define II 2048
#define EE 8
#define KW 5
#define OUTF 3072          // G*F
#define NT 8192            // B*S

// ---------------- scratch (static __device__, no allocation) ----------------
__device__ float g_xT[NT * FF];            // [token, F]           32 MB
__device__ float g_h0tok[NT * II];         // [token, I]           64 MB
__device__ float g_h0cs[BB * II * SS];     // [b, c, s] relu'd     64 MB
__device__ float g_h1tok[NT * II];         // [token, I] relu'd    64 MB
__device__ float g_h2tok[NT * OUTF];       // [token, 3F]          96 MB
__device__ int   g_cnt0[EE];
__device__ int   g_cnt2[EE];
__device__ int   g_list0[EE * NT];
__device__ int   g_list2[EE * NT];

// ---------------- utilities ----------------
__global__ void zero_counts_kernel() {
    if (threadIdx.x < EE) { g_cnt0[threadIdx.x] = 0; g_cnt2[threadIdx.x] = 0; }
}

// inp [B,F,S] -> xT [B*S, F]
__global__ void transpose_in_kernel(const float* __restrict__ in, float* __restrict__ xT) {
    __shared__ float tile[32][33];
    const int b = blockIdx.z;
    const int f0 = blockIdx.y * 32, s0 = blockIdx.x * 32;
    const int tx = threadIdx.x, ty = threadIdx.y;
    #pragma unroll
    for (int r = 0; r < 32; r += 8)
        tile[ty + r][tx] = in[((size_t)b * FF + f0 + ty + r) * SS + s0 + tx];
    __syncthreads();
    #pragma unroll
    for (int r = 0; r < 32; r += 8)
        xT[((size_t)b * SS + s0 + ty + r) * FF + f0 + tx] = tile[tx][ty + r];
}

// h0tok [B*S, I] -> h0cs [B, I, S] with relu
__global__ void transpose_relu_kernel(const float* __restrict__ h0tok, float* __restrict__ h0cs) {
    __shared__ float tile[32][33];
    const int b = blockIdx.z;
    const int i0 = blockIdx.y * 32, s0 = blockIdx.x * 32;
    const int tx = threadIdx.x, ty = threadIdx.y;
    #pragma unroll
    for (int r = 0; r < 32; r += 8)
        tile[ty + r][tx] = h0tok[((size_t)b * SS + s0 + ty + r) * II + i0 + tx];
    __syncthreads();
    #pragma unroll
    for (int r = 0; r < 32; r += 8)
        h0cs[((size_t)b * II + i0 + ty + r) * SS + s0 + tx] = fmaxf(tile[tx][ty + r], 0.0f);
}

// ---------------- gating: logits + argmax + per-expert token lists ----------------
template<int KD>
__global__ __launch_bounds__(256) void gate_kernel(const float* __restrict__ X,
                                                   const float* __restrict__ Gw,
                                                   int* __restrict__ cnt,
                                                   int* __restrict__ list) {
    const int t = blockIdx.x;
    const float* x = X + (size_t)t * KD;
    float acc[EE];
    #pragma unroll
    for (int e = 0; e < EE; e++) acc[e] = 0.0f;
    for (int f = threadIdx.x; f < KD; f += 256) {
        const float xv = x[f];
        #pragma unroll
        for (int e = 0; e < EE; e++) acc[e] += xv * Gw[e * KD + f];
    }
    __shared__ float red[EE][256];
    #pragma unroll
    for (int e = 0; e < EE; e++) red[e][threadIdx.x] = acc[e];
    __syncthreads();
    for (int srt = 128; srt > 0; srt >>= 1) {
        if (threadIdx.x < srt) {
            #pragma unroll
            for (int e = 0; e < EE; e++) red[e][threadIdx.x] += red[e][threadIdx.x + srt];
        }
        __syncthreads();
    }
    if (threadIdx.x == 0) {
        int best = 0; float bv = red[0][0];
        #pragma unroll
        for (int e = 1; e < EE; e++) { const float v = red[e][0]; if (v > bv) { bv = v; best = e; } }
        const int pos = atomicAdd(&cnt[best], 1);
        list[best * NT + pos] = t;
    }
}

// ---------------- grouped expert GEMM: out[tok, n] = X[tok, :] @ W[e] ----------------
// 64 tokens x 128 n per block, BK=16, 256 threads, 4x8 micro-tile.
template<int KD, int ND>
__global__ __launch_bounds__(256) void moe_gemm_kernel(const float* __restrict__ X,
                                                       const float* __restrict__ W,
                                                       const int* __restrict__ cnt,
                                                       const int* __restrict__ list,
                                                       float* __restrict__ out) {
    const int e = blockIdx.z;
    const int ce = cnt[e];
    const int m0 = blockIdx.y * 64;
    if (m0 >= ce) return;
    const int n0 = blockIdx.x * 128;
    const float* We = W + (size_t)e * KD * ND;

    __shared__ int   toks[64];
    __shared__ float As[16][68];
    __shared__ float Bs[16][132];

    const int tid = threadIdx.x;
    if (tid < 64) {
        const int m = m0 + tid;
        toks[tid] = list[e * NT + (m < ce ? m : m0)];
    }
    __syncthreads();

    const int tx = tid & 15, ty = tid >> 4;
    const int la_m = tid >> 2;
    const int la_k = (tid & 3) << 2;
    const int lb_k = tid >> 4;
    const int lb_n = (tid & 15) << 3;
    const float* xrow = X + (size_t)toks[la_m] * KD + la_k;

    float acc[4][8];
    #pragma unroll
    for (int i = 0; i < 4; i++)
        #pragma unroll
        for (int j = 0; j < 8; j++) acc[i][j] = 0.0f;

    for (int k0 = 0; k0 < KD; k0 += 16) {
        const float4 av = *(const float4*)(xrow + k0);
        As[la_k + 0][la_m] = av.x;
        As[la_k + 1][la_m] = av.y;
        As[la_k + 2][la_m] = av.z;
        As[la_k + 3][la_m] = av.w;
        const float* wp = We + (size_t)(k0 + lb_k) * ND + n0 + lb_n;
        *(float4*)&Bs[lb_k][lb_n]     = *(const float4*)wp;
        *(float4*)&Bs[lb_k][lb_n + 4] = *(const float4*)(wp + 4);
        __syncthreads();
        #pragma unroll
        for (int kk = 0; kk < 16; kk++) {
            const float4 a  = *(const float4*)&As[kk][ty << 2];
            const float4 b0 = *(const float4*)&Bs[kk][tx << 3];
            const float4 b1 = *(const float4*)&Bs[kk][(tx << 3) + 4];
            const float avv[4] = {a.x, a.y, a.z, a.w};
            const float bvv[8] = {b0.x, b0.y, b0.z, b0.w, b1.x, b1.y, b1.z, b1.w};
            #pragma unroll
            for (int i = 0; i < 4; i++)
                #pragma unroll
                for (int j = 0; j < 8; j++) acc[i][j] += avv[i] * bvv[j];
        }
        __syncthreads();
    }
    #pragma unroll
    for (int i = 0; i < 4; i++) {
        const int m = m0 + (ty << 2) + i;
        if (m < ce) {
            float* dst = out + (size_t)toks[(ty << 2) + i] * ND + n0 + (tx << 3);
            *(float4*)dst       = make_float4(acc[i][0], acc[i][1], acc[i][2], acc[i][3]);
            *((float4*)dst + 1) = make_float4(acc[i][4], acc[i][5], acc[i][6], acc[i][7]);
        }
    }
}

// ---------------- causal conv as implicit-im2col GEMM + relu, token-major out ----------------
// out[b,o,s] = sum_{c,k} W1[o,c,k] * h0cs[b,c,s+k-4];  writes relu to h1tok[(b*S+s)*I + o]
__global__ __launch_bounds__(256) void conv_kernel(const float* __restrict__ Xc,
                                                   const float* __restrict__ W1,
                                                   float* __restrict__ Ytok) {
    const int s0 = blockIdx.x * 64;
    const int b  = blockIdx.y;
    const int o0 = blockIdx.z * 128;

    __shared__ float Ws[80][132];   // [cc*5+k][o]
    __shared__ float Xs[16][72];    // [cc][j], j in [0,68): s = s0-4+j

    const int tid = threadIdx.x;
    const int tx = tid & 15, ty = tid >> 4;

    float acc[8][4];
    #pragma unroll
    for (int i = 0; i < 8; i++)
        #pragma unroll
        for (int j = 0; j < 4; j++) acc[i][j] = 0.0f;

    const float* w1base = W1 + (size_t)o0 * (II * KW);
    const float* xbase  = Xc + (size_t)b * II * SS;

    for (int c0 = 0; c0 < II; c0 += 16) {
        for (int idx = tid; idx < 128 * 80; idx += 256) {
            const int o = idx / 80;
            const int r = idx - o * 80;                 // r = cc*5 + k
            Ws[r][o] = w1base[(size_t)o * (II * KW) + c0 * KW + r];
        }
        for (int idx = tid; idx < 16 * 68; idx += 256) {
            const int cc = idx / 68;
            const int j  = idx - cc * 68;
            const int s  = s0 + j - 4;
            Xs[cc][j] = (s >= 0) ? xbase[(size_t)(c0 + cc) * SS + s] : 0.0f;
        }
        __syncthreads();
        #pragma unroll 4
        for (int cc = 0; cc < 16; cc++) {
            float xr[8];
            const float4 xa = *(const float4*)&Xs[cc][tx << 2];
            const float4 xb = *(const float4*)&Xs[cc][(tx << 2) + 4];
            xr[0] = xa.x; xr[1] = xa.y; xr[2] = xa.z; xr[3] = xa.w;
            xr[4] = xb.x; xr[5] = xb.y; xr[6] = xb.z; xr[7] = xb.w;
            #pragma unroll
            for (int k = 0; k < KW; k++) {
                const float4 wa = *(const float4*)&Ws[cc * KW + k][ty << 3];
                const float4 wb = *(const float4*)&Ws[cc * KW + k][(ty << 3) + 4];
                const float wr[8] = {wa.x, wa.y, wa.z, wa.w, wb.x, wb.y, wb.z, wb.w};
                #pragma unroll
                for (int i = 0; i < 8; i++)
                    #pragma unroll
                    for (int j = 0; j < 4; j++)
                        acc[i][j] += wr[i] * xr[j + k];
            }
        }
        __syncthreads();
    }
    #pragma unroll
    for (int j = 0; j < 4; j++) {
        const int s = s0 + (tx << 2) + j;
        float* dst = Ytok + ((size_t)b * SS + s) * II + o0 + (ty << 3);
        *(float4*)dst = make_float4(fmaxf(acc[0][j], 0.f), fmaxf(acc[1][j], 0.f),
                                    fmaxf(acc[2][j], 0.f), fmaxf(acc[3][j], 0.f));
        *((float4*)dst + 1) = make_float4(fmaxf(acc[4][j], 0.f), fmaxf(acc[5][j], 0.f),
                                          fmaxf(acc[6][j], 0.f), fmaxf(acc[7][j], 0.f));
    }
}

// ---------------- cumsum(feature) / divisor * scale + shift, center, norm, *0.25 ----------------
__global__ __launch_bounds__(256) void final_kernel(const float* __restrict__ H,
                                                    const float* __restrict__ divisor,
                                                    float* __restrict__ out) {
    const int t = blockIdx.x;
    const int b = t >> 11;          // t / SS
    const int s = t & (SS - 1);
    const float* h = H + (size_t)t * OUTF;
    const int tid = threadIdx.x;
    const int lane = tid & 31, wid = tid >> 5;

    // thread-local inclusive prefix over 4 consecutive depth values
    const float4 d4 = *(const float4*)(h + (tid << 2));
    const float v0 = d4.x;
    const float v1 = v0 + d4.y;
    const float v2 = v1 + d4.z;
    const float v3 = v2 + d4.w;
    const float tsum = v3;

    // warp inclusive scan of thread sums
    float xsc = tsum;
    #pragma unroll
    for (int o = 1; o < 32; o <<= 1) {
        const float y = __shfl_up_sync(0xffffffffu, xsc, o);
        if (lane >= o) xsc += y;
    }
    __shared__ float wsum[8];
    __shared__ float woff[8];
    if (lane == 31) wsum[wid] = xsc;
    __syncthreads();
    if (tid == 0) { float r = 0.f; for (int w = 0; w < 8; w++) { woff[w] = r; r += wsum[w]; } }
    __syncthreads();
    const float off = woff[wid] + (xsc - tsum);

    const float invd = 1.0f / divisor[s];
    const float4 sc  = *(const float4*)(h + FF + (tid << 2));
    const float4 sh  = *(const float4*)(h + 2 * FF + (tid << 2));
    const float o0 = (v0 + off) * invd * sc.x + sh.x;
    const float o1 = (v1 + off) * invd * sc.y + sh.y;
    const float o2 = (v2 + off) * invd * sc.z + sh.z;
    const float o3 = (v3 + off) * invd * sc.w + sh.w;

    // mean over features
    float s1 = o0 + o1 + o2 + o3;
    #pragma unroll
    for (int o = 16; o > 0; o >>= 1) s1 += __shfl_xor_sync(0xffffffffu, s1, o);
    __shared__ float r1[8];
    __shared__ float s_mean;
    if (lane == 0) r1[wid] = s1;
    __syncthreads();
    if (tid == 0) { float a = 0.f; for (int w = 0; w < 8; w++) a += r1[w]; s_mean = a * (1.0f / FF); }
    __syncthreads();
    const float mean = s_mean;

    // centered norm
    const float c0 = o0 - mean, c1 = o1 - mean, c2 = o2 - mean, c3 = o3 - mean;
    float s2 = c0 * c0 + c1 * c1 + c2 * c2 + c3 * c3;
    #pragma unroll
    for (int o = 16; o > 0; o >>= 1) s2 += __shfl_xor_sync(0xffffffffu, s2, o);
    __shared__ float r2[8];
    __shared__ float s_scale;
    if (lane == 0) r2[wid] = s2;
    __syncthreads();
    if (tid == 0) {
        float a = 0.f;
        for (int w = 0; w < 8; w++) a += r2[w];
        const float denom = sqrtf(a) * (1.0f / 32.0f) + 1e-5f;  // ||c|| * F^-0.5 + eps
        s_scale = 0.25f / denom;                                // * INIT_SCALE
    }
    __syncthreads();
    const float k = s_scale;

    float* op = out + ((size_t)b * FF + (tid << 2)) * SS + s;
    op[0]          = c0 * k;
    op[SS]         = c1 * k;
    op[2 * (size_t)SS] = c2 * k;
    op[3 * (size_t)SS] = c3 * k;
}

// ---------------- launch ----------------
extern "C" void kernel_launch(void* const* d_in, const int* in_sizes, int n_in,
                              void* d_out, int out_size) {
    (void)in_sizes; (void)n_in; (void)out_size;
    const float* inp     = (const float*)d_in[0];
    const float* divisor = (const float*)d_in[1];
    const float* w0g     = (const float*)d_in[2];
    const float* w0      = (const float*)d_in[3];
    const float* w1      = (const float*)d_in[4];
    const float* w2g     = (const float*)d_in[5];
    const float* w2      = (const float*)d_in[6];
    float* out = (float*)d_out;

    float *xT, *h0tok, *h0cs, *h1tok, *h2tok;
    int *cnt0, *cnt2, *list0, *list2;
    cudaGetSymbolAddress((void**)&xT,    g_xT);
    cudaGetSymbolAddress((void**)&h0tok, g_h0tok);
    cudaGetSymbolAddress((void**)&h0cs,  g_h0cs);
    cudaGetSymbolAddress((void**)&h1tok, g_h1tok);
    cudaGetSymbolAddress((void**)&h2tok, g_h2tok);
    cudaGetSymbolAddress((void**)&cnt0,  g_cnt0);
    cudaGetSymbolAddress((void**)&cnt2,  g_cnt2);
    cudaGetSymbolAddress((void**)&list0, g_list0);
    cudaGetSymbolAddress((void**)&list2, g_list2);

    zero_counts_kernel<<<1, 32>>>();
    transpose_in_kernel<<<dim3(SS / 32, FF / 32, BB), dim3(32, 8)>>>(inp, xT);
    gate_kernel<FF><<<NT, 256>>>(xT, w0g, cnt0, list0);
    moe_gemm_kernel<FF, II><<<dim3(II / 128, NT / 64, EE), 256>>>(xT, w0, cnt0, list0, h0tok);
    transpose_relu_kernel<<<dim3(SS / 32, II / 32, BB), dim3(32, 8)>>>(h0tok, h0cs);
    conv_kernel<<<dim3(SS / 64, BB, II / 128), 256>>>(h0cs, w1, h1tok);
    gate_kernel<II><<<NT, 256>>>(h1tok, w2g, cnt2, list2);
    moe_gemm_kernel<II, OUTF><<<dim3(OUTF / 128, NT / 64, EE), 256>>>(h1tok, w2, cnt2, list2, h2tok);
    final_kernel<<<NT, 256>>>(h2tok, divisor, out);
}

// round 5
// speedup vs baseline: 1.7016x; 1.6977x over previous
#include <cuda_runtime.h>
#include <math.h>

#define BB 4
#define FF 1024
#define SS 2048
#define II 2048
#define EE 8
#define KW 5
#define OUTF 3072          // G*F
#define NT 8192            // B*S

typedef unsigned long long u64;

// ---------------- f32x2 helpers (Blackwell packed fp32, exact .rn per lane) ----------------
__device__ __forceinline__ u64 pk2(float lo, float hi) {
    u64 r; asm("mov.b64 %0, {%1, %2};" : "=l"(r) : "f"(lo), "f"(hi)); return r;
}
__device__ __forceinline__ u64 dup2(float v) { return pk2(v, v); }
__device__ __forceinline__ void fma2(u64& d, u64 a, u64 b) {
    asm("fma.rn.f32x2 %0, %1, %2, %0;" : "+l"(d) : "l"(a), "l"(b));
}
__device__ __forceinline__ float2 upk2(u64 v) {
    float2 f; asm("mov.b64 {%0, %1}, %2;" : "=f"(f.x), "=f"(f.y) : "l"(v)); return f;
}

// ---------------- scratch (static __device__, no allocation) ----------------
__device__ float g_xT[NT * FF];            // [token, F]
__device__ float g_h0tok[NT * II];         // [token, I]
__device__ float g_h0cs[BB * II * SS];     // [b, c, s] relu'd
__device__ float g_h1tok[NT * II];         // [token, I] relu'd
__device__ float g_h2tok[NT * OUTF];       // [token, 3F]
__device__ float g_w1t[KW * II * II];      // W1 transposed: [k][c][o]
__device__ int   g_cnt0[EE];
__device__ int   g_cnt2[EE];
__device__ int   g_list0[EE * NT];
__device__ int   g_list2[EE * NT];

// ---------------- utilities ----------------
__global__ void zero_counts_kernel() {
    if (threadIdx.x < EE) { g_cnt0[threadIdx.x] = 0; g_cnt2[threadIdx.x] = 0; }
}

// inp [B,F,S] -> xT [B*S, F]
__global__ void transpose_in_kernel(const float* __restrict__ in, float* __restrict__ xT) {
    __shared__ float tile[32][33];
    const int b = blockIdx.z;
    const int f0 = blockIdx.y * 32, s0 = blockIdx.x * 32;
    const int tx = threadIdx.x, ty = threadIdx.y;
    #pragma unroll
    for (int r = 0; r < 32; r += 8)
        tile[ty + r][tx] = in[((size_t)b * FF + f0 + ty + r) * SS + s0 + tx];
    __syncthreads();
    #pragma unroll
    for (int r = 0; r < 32; r += 8)
        xT[((size_t)b * SS + s0 + ty + r) * FF + f0 + tx] = tile[tx][ty + r];
}

// h0tok [B*S, I] -> h0cs [B, I, S] with relu
__global__ void transpose_relu_kernel(const float* __restrict__ h0tok, float* __restrict__ h0cs) {
    __shared__ float tile[32][33];
    const int b = blockIdx.z;
    const int i0 = blockIdx.y * 32, s0 = blockIdx.x * 32;
    const int tx = threadIdx.x, ty = threadIdx.y;
    #pragma unroll
    for (int r = 0; r < 32; r += 8)
        tile[ty + r][tx] = h0tok[((size_t)b * SS + s0 + ty + r) * II + i0 + tx];
    __syncthreads();
    #pragma unroll
    for (int r = 0; r < 32; r += 8)
        h0cs[((size_t)b * II + i0 + ty + r) * SS + s0 + tx] = fmaxf(tile[tx][ty + r], 0.0f);
}

// W1 [O][C][K] -> W1t [K][C][O]
__global__ void transpose_w1_kernel(const float* __restrict__ w1, float* __restrict__ wt) {
    __shared__ float tile[32][33];
    const int k  = blockIdx.z;
    const int c0 = blockIdx.y * 32, o0 = blockIdx.x * 32;
    const int tx = threadIdx.x, ty = threadIdx.y;
    #pragma unroll
    for (int r = 0; r < 32; r += 8)
        tile[ty + r][tx] = w1[((size_t)(o0 + ty + r) * II + c0 + tx) * KW + k];
    __syncthreads();
    #pragma unroll
    for (int r = 0; r < 32; r += 8)
        wt[((size_t)k * II + c0 + ty + r) * II + o0 + tx] = tile[tx][ty + r];
}

// ---------------- gating: logits + argmax + per-expert token lists ----------------
template<int KD>
__global__ __launch_bounds__(256) void gate_kernel(const float* __restrict__ X,
                                                   const float* __restrict__ Gw,
                                                   int* __restrict__ cnt,
                                                   int* __restrict__ list) {
    const int t = blockIdx.x;
    const float* x = X + (size_t)t * KD;
    float acc[EE];
    #pragma unroll
    for (int e = 0; e < EE; e++) acc[e] = 0.0f;
    for (int f = threadIdx.x; f < KD; f += 256) {
        const float xv = x[f];
        #pragma unroll
        for (int e = 0; e < EE; e++) acc[e] += xv * Gw[e * KD + f];
    }
    __shared__ float red[EE][256];
    #pragma unroll
    for (int e = 0; e < EE; e++) red[e][threadIdx.x] = acc[e];
    __syncthreads();
    for (int srt = 128; srt > 0; srt >>= 1) {
        if (threadIdx.x < srt) {
            #pragma unroll
            for (int e = 0; e < EE; e++) red[e][threadIdx.x] += red[e][threadIdx.x + srt];
        }
        __syncthreads();
    }
    if (threadIdx.x == 0) {
        int best = 0; float bv = red[0][0];
        #pragma unroll
        for (int e = 1; e < EE; e++) { const float v = red[e][0]; if (v > bv) { bv = v; best = e; } }
        const int pos = atomicAdd(&cnt[best], 1);
        list[best * NT + pos] = t;
    }
}

// ---------------- grouped expert GEMM: 128 tok x 128 n, BK=16, 256 thr, 8x8 micro (f32x2) ----
template<int KD, int ND>
__global__ __launch_bounds__(256) void moe_gemm_kernel(const float* __restrict__ X,
                                                       const float* __restrict__ W,
                                                       const int* __restrict__ cnt,
                                                       const int* __restrict__ list,
                                                       float* __restrict__ out) {
    const int e = blockIdx.z;
    const int ce = cnt[e];
    const int m0 = blockIdx.y * 128;
    if (m0 >= ce) return;
    const int n0 = blockIdx.x * 128;
    const float* We = W + (size_t)e * KD * ND;

    __shared__ int   toks[128];
    __shared__ float As[2][16][132];
    __shared__ float Bs[2][16][128];

    const int tid = threadIdx.x;
    if (tid < 128) {
        const int m = m0 + tid;
        toks[tid] = list[e * NT + (m < ce ? m : ce - 1)];
    }
    __syncthreads();

    const int tx = tid & 15, ty = tid >> 4;
    const int la_m = tid >> 1;
    const int la_k = (tid & 1) << 3;            // 8 floats per thread
    const int lb_k = tid >> 4;
    const int lb_n = (tid & 15) << 3;
    const float* xrow = X + (size_t)toks[la_m] * KD + la_k;

    u64 acc2[8][4];
    #pragma unroll
    for (int i = 0; i < 8; i++)
        #pragma unroll
        for (int j = 0; j < 4; j++) acc2[i][j] = 0ull;

    // --- stage 0 load ---
    {
        const float4 pa0 = *(const float4*)(xrow);
        const float4 pa1 = *(const float4*)(xrow + 4);
        const float* wp = We + (size_t)lb_k * ND + n0 + lb_n;
        const float4 pb0 = *(const float4*)wp;
        const float4 pb1 = *(const float4*)(wp + 4);
        const float pav[8] = {pa0.x, pa0.y, pa0.z, pa0.w, pa1.x, pa1.y, pa1.z, pa1.w};
        #pragma unroll
        for (int t = 0; t < 8; t++) As[0][la_k + t][la_m] = pav[t];
        *(float4*)&Bs[0][lb_k][lb_n]     = pb0;
        *(float4*)&Bs[0][lb_k][lb_n + 4] = pb1;
    }
    __syncthreads();

    int buf = 0;
    for (int k0 = 16; k0 < KD + 16; k0 += 16) {
        const bool nxt = (k0 < KD);
        float4 pa0, pa1, pb0, pb1;
        if (nxt) {
            pa0 = *(const float4*)(xrow + k0);
            pa1 = *(const float4*)(xrow + k0 + 4);
            const float* wp = We + (size_t)(k0 + lb_k) * ND + n0 + lb_n;
            pb0 = *(const float4*)wp;
            pb1 = *(const float4*)(wp + 4);
        }
        // compute on buf
        #pragma unroll 8
        for (int kk = 0; kk < 16; kk++) {
            const float4 a0 = *(const float4*)&As[buf][kk][ty << 3];
            const float4 a1 = *(const float4*)&As[buf][kk][(ty << 3) + 4];
            const float4 b0 = *(const float4*)&Bs[buf][kk][tx << 3];
            const float4 b1 = *(const float4*)&Bs[buf][kk][(tx << 3) + 4];
            u64 bb[4];
            bb[0] = pk2(b0.x, b0.y); bb[1] = pk2(b0.z, b0.w);
            bb[2] = pk2(b1.x, b1.y); bb[3] = pk2(b1.z, b1.w);
            const float av[8] = {a0.x, a0.y, a0.z, a0.w, a1.x, a1.y, a1.z, a1.w};
            #pragma unroll
            for (int i = 0; i < 8; i++) {
                const u64 ad = dup2(av[i]);
                #pragma unroll
                for (int j = 0; j < 4; j++) fma2(acc2[i][j], ad, bb[j]);
            }
        }
        if (nxt) {
            const int nb = buf ^ 1;
            const float pav[8] = {pa0.x, pa0.y, pa0.z, pa0.w, pa1.x, pa1.y, pa1.z, pa1.w};
            #pragma unroll
            for (int t = 0; t < 8; t++) As[nb][la_k + t][la_m] = pav[t];
            *(float4*)&Bs[nb][lb_k][lb_n]     = pb0;
            *(float4*)&Bs[nb][lb_k][lb_n + 4] = pb1;
            __syncthreads();
            buf = nb;
        }
    }

    #pragma unroll
    for (int i = 0; i < 8; i++) {
        const int m = m0 + (ty << 3) + i;
        if (m < ce) {
            float* dst = out + (size_t)toks[(ty << 3) + i] * ND + n0 + (tx << 3);
            const float2 f0 = upk2(acc2[i][0]), f1 = upk2(acc2[i][1]);
            const float2 f2 = upk2(acc2[i][2]), f3 = upk2(acc2[i][3]);
            *(float4*)dst       = make_float4(f0.x, f0.y, f1.x, f1.y);
            *((float4*)dst + 1) = make_float4(f2.x, f2.y, f3.x, f3.y);
        }
    }
}

// ---------------- causal conv: cp.async double-buffered, f32x2, relu, token-major out -------
// Wt: [K][C][O]; out[b,o,s] = sum_{c,k} Wt[k][c][o] * x[b,c,s+k-4]
#define CONV_WS_FLOATS (80 * 128)
#define CONV_XS_FLOATS (16 * 68)
#define CONV_SMEM_BYTES ((2 * CONV_WS_FLOATS + 2 * CONV_XS_FLOATS) * 4)

__global__ __launch_bounds__(256) void conv_kernel(const float* __restrict__ Wt,
                                                   const float* __restrict__ Xc,
                                                   float* __restrict__ Ytok) {
    extern __shared__ float dynsm[];
    float* WsB = dynsm;                          // [2][80][128]
    float* XsB = dynsm + 2 * CONV_WS_FLOATS;     // [2][16][68]

    const int s0 = blockIdx.x * 64;
    const int b  = blockIdx.y;
    const int o0 = blockIdx.z * 128;
    const int tid = threadIdx.x;
    const int tx = tid & 15, ty = tid >> 4;
    const float* xbase = Xc + (size_t)b * II * SS;

    u64 acc2[4][4];
    #pragma unroll
    for (int p = 0; p < 4; p++)
        #pragma unroll
        for (int j = 0; j < 4; j++) acc2[p][j] = 0ull;

    // issue cp.async loads for channel chunk c0 into buffer `bf`
    auto issue = [&](int c0, int bf) {
        #pragma unroll
        for (int t = 0; t < 10; t++) {           // 80 rows x 128 floats = 2560 16B chunks
            const int idx = tid + t * 256;
            const int row = idx >> 5;            // cc*5 + k
            const int ch  = (idx & 31) << 2;
            const int cc  = row / 5;
            const int k   = row - cc * 5;
            const float* src = Wt + ((size_t)k * II + (c0 + cc)) * II + o0 + ch;
            const unsigned dst = (unsigned)__cvta_generic_to_shared(WsB + (bf * 80 + row) * 128 + ch);
            asm volatile("cp.async.cg.shared.global [%0], [%1], 16;\n" :: "r"(dst), "l"(src));
        }
        #pragma unroll
        for (int t = 0; t < 5; t++) {            // 16 x 68 floats, 4B with zfill for s<0
            const int idx = tid + t * 256;
            if (idx < 16 * 68) {
                const int cc = idx / 68, j = idx - cc * 68;
                const int s  = s0 + j - 4;
                const float* src = xbase + (size_t)(c0 + cc) * SS + s;
                const unsigned dst = (unsigned)__cvta_generic_to_shared(XsB + (bf * 16 + cc) * 68 + j);
                const int pz = (s >= 0) ? 4 : 0;
                asm volatile("cp.async.ca.shared.global [%0], [%1], 4, %2;\n"
                             :: "r"(dst), "l"(src), "r"(pz));
            }
        }
        asm volatile("cp.async.commit_group;\n");
    };

    issue(0, 0);
    int buf = 0;
    for (int c0 = 0; c0 < II; c0 += 16) {
        const bool nxt = (c0 + 16 < II);
        if (nxt) issue(c0 + 16, buf ^ 1);
        if (nxt) asm volatile("cp.async.wait_group 1;\n");
        else     asm volatile("cp.async.wait_group 0;\n");
        __syncthreads();

        const float* Wsb = WsB + buf * CONV_WS_FLOATS;
        const float* Xsb = XsB + buf * CONV_XS_FLOATS;
        #pragma unroll 4
        for (int cc = 0; cc < 16; cc++) {
            const float4 x0 = *(const float4*)(Xsb + cc * 68 + (tx << 2));
            const float4 x1 = *(const float4*)(Xsb + cc * 68 + (tx << 2) + 4);
            u64 xd[8];
            xd[0] = dup2(x0.x); xd[1] = dup2(x0.y); xd[2] = dup2(x0.z); xd[3] = dup2(x0.w);
            xd[4] = dup2(x1.x); xd[5] = dup2(x1.y); xd[6] = dup2(x1.z); xd[7] = dup2(x1.w);
            #pragma unroll
            for (int k = 0; k < KW; k++) {
                const float4 wa = *(const float4*)(Wsb + (cc * 5 + k) * 128 + (ty << 3));
                const float4 wb = *(const float4*)(Wsb + (cc * 5 + k) * 128 + (ty << 3) + 4);
                const u64 w0 = pk2(wa.x, wa.y), w1 = pk2(wa.z, wa.w);
                const u64 w2 = pk2(wb.x, wb.y), w3 = pk2(wb.z, wb.w);
                #pragma unroll
                for (int j = 0; j < 4; j++) {
                    fma2(acc2[0][j], w0, xd[j + k]);
                    fma2(acc2[1][j], w1, xd[j + k]);
                    fma2(acc2[2][j], w2, xd[j + k]);
                    fma2(acc2[3][j], w3, xd[j + k]);
                }
            }
        }
        __syncthreads();
        buf ^= 1;
    }

    #pragma unroll
    for (int j = 0; j < 4; j++) {
        const int s = s0 + (tx << 2) + j;
        float* dst = Ytok + ((size_t)b * SS + s) * II + o0 + (ty << 3);
        const float2 f0 = upk2(acc2[0][j]), f1 = upk2(acc2[1][j]);
        const float2 f2 = upk2(acc2[2][j]), f3 = upk2(acc2[3][j]);
        *(float4*)dst = make_float4(fmaxf(f0.x, 0.f), fmaxf(f0.y, 0.f),
                                    fmaxf(f1.x, 0.f), fmaxf(f1.y, 0.f));
        *((float4*)dst + 1) = make_float4(fmaxf(f2.x, 0.f), fmaxf(f2.y, 0.f),
                                          fmaxf(f3.x, 0.f), fmaxf(f3.y, 0.f));
    }
}

// ---------------- cumsum(feature) / divisor * scale + shift, center, norm, *0.25 ----------------
__global__ __launch_bounds__(256) void final_kernel(const float* __restrict__ H,
                                                    const float* __restrict__ divisor,
                                                    float* __restrict__ out) {
    const int t = blockIdx.x;
    const int b = t >> 11;
    const int s = t & (SS - 1);
    const float* h = H + (size_t)t * OUTF;
    const int tid = threadIdx.x;
    const int lane = tid & 31, wid = tid >> 5;

    const float4 d4 = *(const float4*)(h + (tid << 2));
    const float v0 = d4.x;
    const float v1 = v0 + d4.y;
    const float v2 = v1 + d4.z;
    const float v3 = v2 + d4.w;
    const float tsum = v3;

    float xsc = tsum;
    #pragma unroll
    for (int o = 1; o < 32; o <<= 1) {
        const float y = __shfl_up_sync(0xffffffffu, xsc, o);
        if (lane >= o) xsc += y;
    }
    __shared__ float wsum[8];
    __shared__ float woff[8];
    if (lane == 31) wsum[wid] = xsc;
    __syncthreads();
    if (tid == 0) { float r = 0.f; for (int w = 0; w < 8; w++) { woff[w] = r; r += wsum[w]; } }
    __syncthreads();
    const float off = woff[wid] + (xsc - tsum);

    const float invd = 1.0f / divisor[s];
    const float4 sc  = *(const float4*)(h + FF + (tid << 2));
    const float4 sh  = *(const float4*)(h + 2 * FF + (tid << 2));
    const float o0 = (v0 + off) * invd * sc.x + sh.x;
    const float o1 = (v1 + off) * invd * sc.y + sh.y;
    const float o2 = (v2 + off) * invd * sc.z + sh.z;
    const float o3 = (v3 + off) * invd * sc.w + sh.w;

    float s1 = o0 + o1 + o2 + o3;
    #pragma unroll
    for (int o = 16; o > 0; o >>= 1) s1 += __shfl_xor_sync(0xffffffffu, s1, o);
    __shared__ float r1[8];
    __shared__ float s_mean;
    if (lane == 0) r1[wid] = s1;
    __syncthreads();
    if (tid == 0) { float a = 0.f; for (int w = 0; w < 8; w++) a += r1[w]; s_mean = a * (1.0f / FF); }
    __syncthreads();
    const float mean = s_mean;

    const float c0 = o0 - mean, c1 = o1 - mean, c2 = o2 - mean, c3 = o3 - mean;
    float s2 = c0 * c0 + c1 * c1 + c2 * c2 + c3 * c3;
    #pragma unroll
    for (int o = 16; o > 0; o >>= 1) s2 += __shfl_xor_sync(0xffffffffu, s2, o);
    __shared__ float r2[8];
    __shared__ float s_scale;
    if (lane == 0) r2[wid] = s2;
    __syncthreads();
    if (tid == 0) {
        float a = 0.f;
        for (int w = 0; w < 8; w++) a += r2[w];
        const float denom = sqrtf(a) * (1.0f / 32.0f) + 1e-5f;
        s_scale = 0.25f / denom;
    }
    __syncthreads();
    const float k = s_scale;

    float* op = out + ((size_t)b * FF + (tid << 2)) * SS + s;
    op[0]              = c0 * k;
    op[SS]             = c1 * k;
    op[2 * (size_t)SS] = c2 * k;
    op[3 * (size_t)SS] = c3 * k;
}

// ---------------- launch ----------------
extern "C" void kernel_launch(void* const* d_in, const int* in_sizes, int n_in,
                              void* d_out, int out_size) {
    (void)in_sizes; (void)n_in; (void)out_size;
    const float* inp     = (const float*)d_in[0];
    const float* divisor = (const float*)d_in[1];
    const float* w0g     = (const float*)d_in[2];
    const float* w0      = (const float*)d_in[3];
    const float* w1      = (const float*)d_in[4];
    const float* w2g     = (const float*)d_in[5];
    const float* w2      = (const float*)d_in[6];
    float* out = (float*)d_out;

    float *xT, *h0tok, *h0cs, *h1tok, *h2tok, *w1t;
    int *cnt0, *cnt2, *list0, *list2;
    cudaGetSymbolAddress((void**)&xT,    g_xT);
    cudaGetSymbolAddress((void**)&h0tok, g_h0tok);
    cudaGetSymbolAddress((void**)&h0cs,  g_h0cs);
    cudaGetSymbolAddress((void**)&h1tok, g_h1tok);
    cudaGetSymbolAddress((void**)&h2tok, g_h2tok);
    cudaGetSymbolAddress((void**)&w1t,   g_w1t);
    cudaGetSymbolAddress((void**)&cnt0,  g_cnt0);
    cudaGetSymbolAddress((void**)&cnt2,  g_cnt2);
    cudaGetSymbolAddress((void**)&list0, g_list0);
    cudaGetSymbolAddress((void**)&list2, g_list2);

    static int smem_set = 0;
    if (!smem_set) {
        cudaFuncSetAttribute(conv_kernel, cudaFuncAttributeMaxDynamicSharedMemorySize,
                             CONV_SMEM_BYTES);
        smem_set = 1;
    }

    zero_counts_kernel<<<1, 32>>>();
    transpose_w1_kernel<<<dim3(II / 32, II / 32, KW), dim3(32, 8)>>>(w1, w1t);
    transpose_in_kernel<<<dim3(SS / 32, FF / 32, BB), dim3(32, 8)>>>(inp, xT);
    gate_kernel<FF><<<NT, 256>>>(xT, w0g, cnt0, list0);
    moe_gemm_kernel<FF, II><<<dim3(II / 128, NT / 128, EE), 256>>>(xT, w0, cnt0, list0, h0tok);
    transpose_relu_kernel<<<dim3(SS / 32, II / 32, BB), dim3(32, 8)>>>(h0tok, h0cs);
    conv_kernel<<<dim3(SS / 64, BB, II / 128), 256, CONV_SMEM_BYTES>>>(w1t, h0cs, h1tok);
    gate_kernel<II><<<NT, 256>>>(h1tok, w2g, cnt2, list2);
    moe_gemm_kernel<II, OUTF><<<dim3(OUTF / 128, NT / 128, EE), 256>>>(h1tok, w2, cnt2, list2, h2tok);
    final_kernel<<<NT, 256>>>(h2tok, divisor, out);
}